// round 4
// baseline (speedup 1.0000x reference)
#include <cuda_runtime.h>
#include <cuda_bf16.h>
#include <cstdint>

// ---------------------------------------------------------------------------
// Problem sizes (fixed by the reference)
// ---------------------------------------------------------------------------
constexpr int MROWS = 16384;   // B*S
constexpr int NDIM  = 4096;    // O
constexpr int KDIM  = 4096;    // F
constexpr int NCH   = 4;       // chunks
constexpr int DCH   = 1024;    // K per chunk

// ---------------------------------------------------------------------------
// Scratch (device globals — allocation-free rule)
// ---------------------------------------------------------------------------
__device__ __nv_bfloat16 g_qx[(size_t)MROWS * KDIM];   // 134 MB quantized x (integers in bf16)
__device__ __nv_bfloat16 g_qw[(size_t)NDIM  * KDIM];   // 33 MB quantized w
__device__ int   g_absmax[8];
__device__ float g_sx[4];
__device__ float g_sw;
__device__ float g_comb[4];    // s_x[c] * s_w

// ---------------------------------------------------------------------------
// Small helpers
// ---------------------------------------------------------------------------
__device__ __forceinline__ uint32_t smem_u32(const void* p) {
    uint32_t r;
    asm("{ .reg .u64 t; cvta.to.shared.u64 t, %1; cvt.u32.u64 %0, t; }" : "=r"(r) : "l"(p));
    return r;
}

#define SWZ128(o) ((o) ^ (((o) >> 3) & 0x70))

__device__ __forceinline__ void cp_async16(uint32_t smem, const void* g) {
    asm volatile("cp.async.cg.shared.global [%0], [%1], 16;" :: "r"(smem), "l"(g));
}
#define CP_COMMIT() asm volatile("cp.async.commit_group;" ::: "memory")
#define CP_WAIT(n)  asm volatile("cp.async.wait_group %0;" :: "n"(n) : "memory")

__device__ __forceinline__ void ldmx4(uint32_t* r, uint32_t addr) {
    asm volatile("ldmatrix.sync.aligned.m8n8.x4.shared.b16 {%0,%1,%2,%3}, [%4];"
                 : "=r"(r[0]), "=r"(r[1]), "=r"(r[2]), "=r"(r[3]) : "r"(addr));
}

__device__ __forceinline__ void mma16816(float* c, const uint32_t* a, uint32_t b0, uint32_t b1) {
    asm volatile(
        "mma.sync.aligned.m16n8k16.row.col.f32.bf16.bf16.f32 "
        "{%0,%1,%2,%3}, {%4,%5,%6,%7}, {%8,%9}, {%0,%1,%2,%3};"
        : "+f"(c[0]), "+f"(c[1]), "+f"(c[2]), "+f"(c[3])
        : "r"(a[0]), "r"(a[1]), "r"(a[2]), "r"(a[3]), "r"(b0), "r"(b1));
}

// ---------------------------------------------------------------------------
// Quantization kernels
// ---------------------------------------------------------------------------
__global__ void k_init() {
    if (threadIdx.x < 8) g_absmax[threadIdx.x] = 0;
}

__device__ __forceinline__ void block_atomic_max(float m, int slot) {
    #pragma unroll
    for (int o = 16; o; o >>= 1) m = fmaxf(m, __shfl_xor_sync(0xffffffffu, m, o));
    __shared__ float red[8];
    if ((threadIdx.x & 31) == 0) red[threadIdx.x >> 5] = m;
    __syncthreads();
    if (threadIdx.x < 8) {
        float t = red[threadIdx.x];
        #pragma unroll
        for (int o = 4; o; o >>= 1) t = fmaxf(t, __shfl_xor_sync(0xffu, t, o));
        if (threadIdx.x == 0) atomicMax(&g_absmax[slot], __float_as_int(t));
    }
}

__global__ void k_absmax_x(const float4* __restrict__ x4) {
    const int chunk = blockIdx.y;                 // 4 chunks, 256 float4 per row each
    const int total = MROWS * 256;
    float m = 0.f;
    for (int j = blockIdx.x * blockDim.x + threadIdx.x; j < total; j += gridDim.x * blockDim.x) {
        int r = j >> 8, jc = j & 255;
        float4 v = x4[(size_t)r * 1024 + chunk * 256 + jc];
        m = fmaxf(m, fmaxf(fmaxf(fabsf(v.x), fabsf(v.y)), fmaxf(fabsf(v.z), fabsf(v.w))));
    }
    block_atomic_max(m, chunk);
}

__global__ void k_absmax_w(const float4* __restrict__ w4) {
    const int total = (NDIM * KDIM) / 4;
    float m = 0.f;
    for (int j = blockIdx.x * blockDim.x + threadIdx.x; j < total; j += gridDim.x * blockDim.x) {
        float4 v = w4[j];
        m = fmaxf(m, fmaxf(fmaxf(fabsf(v.x), fabsf(v.y)), fmaxf(fabsf(v.z), fabsf(v.w))));
    }
    block_atomic_max(m, 4);
}

__global__ void k_scales() {
    float sw = fmaxf(__int_as_float(g_absmax[4]) / 127.0f, 1e-8f);
    g_sw = sw;
    for (int c = 0; c < NCH; c++) {
        float sx = fmaxf(__int_as_float(g_absmax[c]) / 127.0f, 1e-8f);
        g_sx[c] = sx;
        g_comb[c] = sx * sw;
    }
}

__device__ __forceinline__ float fq(float v, float s) {
    // round(v/s) half-to-even (matches jnp.round), then clip
    return fminf(fmaxf(rintf(__fdiv_rn(v, s)), -127.f), 127.f);
}
__device__ __forceinline__ uint32_t pack_bf2(float a, float b) {
    uint32_t lo = (uint32_t)__bfloat16_as_ushort(__float2bfloat16_rn(a));
    uint32_t hi = (uint32_t)__bfloat16_as_ushort(__float2bfloat16_rn(b));
    return lo | (hi << 16);
}

__global__ void k_quant_x(const float4* __restrict__ x4) {
    uint2* __restrict__ q = reinterpret_cast<uint2*>(g_qx);
    const int total = (MROWS * KDIM) / 4;
    for (int i = blockIdx.x * blockDim.x + threadIdx.x; i < total; i += gridDim.x * blockDim.x) {
        float4 v = x4[i];
        float s = g_sx[(i & 1023) >> 8];    // chunk = position of this float4 within its row
        float q0 = fq(v.x, s), q1 = fq(v.y, s), q2 = fq(v.z, s), q3 = fq(v.w, s);
        q[i] = make_uint2(pack_bf2(q0, q1), pack_bf2(q2, q3));
    }
}

__global__ void k_quant_w(const float4* __restrict__ w4) {
    uint2* __restrict__ q = reinterpret_cast<uint2*>(g_qw);
    const int total = (NDIM * KDIM) / 4;
    const float s = g_sw;
    for (int i = blockIdx.x * blockDim.x + threadIdx.x; i < total; i += gridDim.x * blockDim.x) {
        float4 v = w4[i];
        float q0 = fq(v.x, s), q1 = fq(v.y, s), q2 = fq(v.z, s), q3 = fq(v.w, s);
        q[i] = make_uint2(pack_bf2(q0, q1), pack_bf2(q2, q3));
    }
}

// ---------------------------------------------------------------------------
// mma.sync bf16 GEMM: out[16384,4096] = sum_c comb[c]*(qx_c @ qw_c^T) + bias
// BM=BN=128, BK=64, 256 threads (2x4 warps, warptile 64x32), cp.async double
// buffer, SW128-swizzled smem, single accumulator + chunk rescale chain.
// ---------------------------------------------------------------------------
constexpr int BM = 128, BN = 128, BK = 64;
constexpr int KITERS = KDIM / BK;          // 64
constexpr int TILE_BYTES = BM * 128;       // 16 KB (128 rows x 128B SW128 rows)
constexpr int SMEM_BYTES = 4 * TILE_BYTES; // 2 buffers x (A + B)

__device__ __forceinline__ void load_tiles(int m0, int n0, int k0,
                                           uint32_t sA, uint32_t sB, int tid) {
    // A: 128 rows x 64 bf16 (128B/row) = 1024 x 16B vectors; same for B.
    #pragma unroll
    for (int i = 0; i < 4; ++i) {
        int v = tid + i * 256;
        int r = v >> 3, c8 = (v & 7) * 8;
        uint32_t off = SWZ128((uint32_t)(r * 128 + c8 * 2));
        cp_async16(sA + off, g_qx + (size_t)(m0 + r) * KDIM + k0 + c8);
        cp_async16(sB + off, g_qw + (size_t)(n0 + r) * KDIM + k0 + c8);
    }
}

__global__ void __launch_bounds__(256, 2)
k_gemm(const float* __restrict__ bias, float* __restrict__ out) {
    extern __shared__ char smem_raw[];
    const int tid = threadIdx.x, wid = tid >> 5, lane = tid & 31;
    const int wm = wid >> 2, wn = wid & 3;          // 2 x 4 warp grid

    const uint32_t sbase = smem_u32(smem_raw);
    const uint32_t sA[2] = { sbase,                  sbase + 2 * TILE_BYTES };
    const uint32_t sB[2] = { sbase + TILE_BYTES,     sbase + 3 * TILE_BYTES };

    const int m0 = blockIdx.y * BM;
    const int n0 = blockIdx.x * BN;

    // ldmatrix lane addressing (bytes within tile, pre-swizzle)
    const int rA = wm * 64 + (lane & 15);            // + mt*16
    const int cA = (lane >> 4) * 16;                 // + ks*32
    const int rB = wn * 32 + ((lane >> 4) << 3) + (lane & 7);   // + nt2*16
    const int cB = ((lane >> 3) & 1) * 16;           // + ks*32

    const float cb0 = g_comb[0], cb1 = g_comb[1], cb2 = g_comb[2], cb3 = g_comb[3];
    const float ratio[3] = { cb0 / cb1, cb1 / cb2, cb2 / cb3 };

    float acc[4][4][4];
    #pragma unroll
    for (int mt = 0; mt < 4; ++mt)
        #pragma unroll
        for (int nt = 0; nt < 4; ++nt)
            #pragma unroll
            for (int r = 0; r < 4; ++r) acc[mt][nt][r] = 0.f;

    load_tiles(m0, n0, 0, sA[0], sB[0], tid);
    CP_COMMIT();

    for (int kt = 0; kt < KITERS; ++kt) {
        const int b = kt & 1;
        if (kt + 1 < KITERS) {
            load_tiles(m0, n0, (kt + 1) * BK, sA[b ^ 1], sB[b ^ 1], tid);
            CP_COMMIT();
            CP_WAIT(1);
        } else {
            CP_WAIT(0);
        }
        __syncthreads();

        #pragma unroll
        for (int ks = 0; ks < 4; ++ks) {
            uint32_t afr[4][4];
            #pragma unroll
            for (int mt = 0; mt < 4; ++mt) {
                uint32_t off = SWZ128((uint32_t)((rA + mt * 16) * 128 + ks * 32 + cA));
                ldmx4(afr[mt], sA[b] + off);
            }
            uint32_t bfr[2][4];
            #pragma unroll
            for (int nt2 = 0; nt2 < 2; ++nt2) {
                uint32_t off = SWZ128((uint32_t)((rB + nt2 * 16) * 128 + ks * 32 + cB));
                ldmx4(bfr[nt2], sB[b] + off);
            }
            #pragma unroll
            for (int mt = 0; mt < 4; ++mt)
                #pragma unroll
                for (int nt = 0; nt < 4; ++nt)
                    mma16816(acc[mt][nt], afr[mt], bfr[nt >> 1][(nt & 1) * 2],
                             bfr[nt >> 1][(nt & 1) * 2 + 1]);
        }
        __syncthreads();

        // chunk boundary: fold comb[c]/comb[c+1] into the single accumulator
        if ((kt & 15) == 15 && kt != KITERS - 1) {
            const float r = ratio[kt >> 4];
            #pragma unroll
            for (int mt = 0; mt < 4; ++mt)
                #pragma unroll
                for (int nt = 0; nt < 4; ++nt)
                    #pragma unroll
                    for (int q = 0; q < 4; ++q) acc[mt][nt][q] *= r;
        }
    }

    // Epilogue: out = cb3 * acc + bias
    #pragma unroll
    for (int mt = 0; mt < 4; ++mt) {
        const int grow = m0 + wm * 64 + mt * 16 + (lane >> 2);
        float* o0 = out + (size_t)grow * NDIM;
        float* o1 = out + (size_t)(grow + 8) * NDIM;
        #pragma unroll
        for (int nt = 0; nt < 4; ++nt) {
            const int gcol = n0 + wn * 32 + nt * 8 + (lane & 3) * 2;
            float2 bv = *reinterpret_cast<const float2*>(bias + gcol);
            float2 v0, v1;
            v0.x = fmaf(cb3, acc[mt][nt][0], bv.x);
            v0.y = fmaf(cb3, acc[mt][nt][1], bv.y);
            v1.x = fmaf(cb3, acc[mt][nt][2], bv.x);
            v1.y = fmaf(cb3, acc[mt][nt][3], bv.y);
            *reinterpret_cast<float2*>(o0 + gcol) = v0;
            *reinterpret_cast<float2*>(o1 + gcol) = v1;
        }
    }
}

// ---------------------------------------------------------------------------
// Launch
// ---------------------------------------------------------------------------
extern "C" void kernel_launch(void* const* d_in, const int* in_sizes, int n_in,
                              void* d_out, int out_size) {
    const float* x = nullptr; const float* w = nullptr; const float* bias = nullptr;
    for (int i = 0; i < n_in; ++i) {
        if      (in_sizes[i] == MROWS * KDIM) x    = (const float*)d_in[i];
        else if (in_sizes[i] == NDIM  * KDIM) w    = (const float*)d_in[i];
        else if (in_sizes[i] == NDIM)         bias = (const float*)d_in[i];
    }
    if (!x)    x    = (const float*)d_in[0];
    if (!w)    w    = (const float*)d_in[1];
    if (!bias) bias = (const float*)d_in[2];

    cudaFuncSetAttribute(k_gemm, cudaFuncAttributeMaxDynamicSharedMemorySize, SMEM_BYTES);

    k_init<<<1, 32>>>();
    k_absmax_x<<<dim3(512, 4), 256>>>((const float4*)x);
    k_absmax_w<<<512, 256>>>((const float4*)w);
    k_scales<<<1, 1>>>();
    k_quant_x<<<2048, 256>>>((const float4*)x);
    k_quant_w<<<1024, 256>>>((const float4*)w);
    k_gemm<<<dim3(NDIM / BN, MROWS / BM), 256, SMEM_BYTES>>>(bias, (float*)d_out);
}